// round 3
// baseline (speedup 1.0000x reference)
#include <cuda_runtime.h>
#include <math.h>

#define E_DIM 1024
#define S_LEN 2048
#define NHEAD 16

// ---------------- scratch (no allocation allowed) ----------------
__device__ float g_qkv[25165824];   // 8192 x 3072
__device__ float g_q2 [8388608];    // 8192 x 1024  (B,S,H,D)
__device__ float g_k2 [8388608];
__device__ float g_v2 [8388608];
__device__ float g_ctx[8388608];    // (B,S,H,D)

// ---------------- SGEMM: C[M,N] = A[M,K] @ B[N,K]^T + bias[N] ----------------
#define BM 128
#define BN 128
#define BK 16

__global__ __launch_bounds__(256, 2)
void sgemm_nt(const float* __restrict__ A, int lda,
              const float* __restrict__ B, int ldb,
              const float* __restrict__ bias,
              float* __restrict__ C, int ldc, int K)
{
    __shared__ float As[BK][BM];
    __shared__ float Bs[BK][BN];

    const int tid = threadIdx.x;
    const int tx = tid & 15;
    const int ty = tid >> 4;

    const float* Ab = A + (size_t)blockIdx.y * BM * lda;
    const float* Bb = B + (size_t)blockIdx.x * BN * ldb;

    const int lr = tid >> 2;            // 0..63
    const int lc = (tid & 3) << 2;      // 0,4,8,12

    float acc[8][8];
#pragma unroll
    for (int j = 0; j < 8; j++)
#pragma unroll
        for (int i = 0; i < 8; i++) acc[j][i] = 0.0f;

    float4 a0 = *(const float4*)(Ab + (size_t)lr * lda + lc);
    float4 a1 = *(const float4*)(Ab + (size_t)(lr + 64) * lda + lc);
    float4 b0 = *(const float4*)(Bb + (size_t)lr * ldb + lc);
    float4 b1 = *(const float4*)(Bb + (size_t)(lr + 64) * ldb + lc);

    for (int k0 = 0; k0 < K; k0 += BK) {
        As[lc + 0][lr]      = a0.x; As[lc + 1][lr]      = a0.y;
        As[lc + 2][lr]      = a0.z; As[lc + 3][lr]      = a0.w;
        As[lc + 0][lr + 64] = a1.x; As[lc + 1][lr + 64] = a1.y;
        As[lc + 2][lr + 64] = a1.z; As[lc + 3][lr + 64] = a1.w;
        Bs[lc + 0][lr]      = b0.x; Bs[lc + 1][lr]      = b0.y;
        Bs[lc + 2][lr]      = b0.z; Bs[lc + 3][lr]      = b0.w;
        Bs[lc + 0][lr + 64] = b1.x; Bs[lc + 1][lr + 64] = b1.y;
        Bs[lc + 2][lr + 64] = b1.z; Bs[lc + 3][lr + 64] = b1.w;
        __syncthreads();

        if (k0 + BK < K) {
            const float* Ap = Ab + (k0 + BK);
            const float* Bp = Bb + (k0 + BK);
            a0 = *(const float4*)(Ap + (size_t)lr * lda + lc);
            a1 = *(const float4*)(Ap + (size_t)(lr + 64) * lda + lc);
            b0 = *(const float4*)(Bp + (size_t)lr * ldb + lc);
            b1 = *(const float4*)(Bp + (size_t)(lr + 64) * ldb + lc);
        }

#pragma unroll 8
        for (int k = 0; k < BK; k++) {
            float ar[8], br[8];
            float4 t;
            t = *(const float4*)&As[k][ty << 2];
            ar[0] = t.x; ar[1] = t.y; ar[2] = t.z; ar[3] = t.w;
            t = *(const float4*)&As[k][64 + (ty << 2)];
            ar[4] = t.x; ar[5] = t.y; ar[6] = t.z; ar[7] = t.w;
            t = *(const float4*)&Bs[k][tx << 2];
            br[0] = t.x; br[1] = t.y; br[2] = t.z; br[3] = t.w;
            t = *(const float4*)&Bs[k][64 + (tx << 2)];
            br[4] = t.x; br[5] = t.y; br[6] = t.z; br[7] = t.w;
#pragma unroll
            for (int j = 0; j < 8; j++)
#pragma unroll
                for (int i = 0; i < 8; i++)
                    acc[j][i] += ar[j] * br[i];
        }
        __syncthreads();
    }

    const int cb0 = blockIdx.x * BN + (tx << 2);
    float4 bi0 = *(const float4*)(bias + cb0);
    float4 bi1 = *(const float4*)(bias + cb0 + 64);
    const size_t rbase = (size_t)blockIdx.y * BM;
#pragma unroll
    for (int j = 0; j < 8; j++) {
        int rr = (j < 4) ? ((ty << 2) + j) : (64 + (ty << 2) + (j - 4));
        float* Cp = C + (rbase + rr) * (size_t)ldc + cb0;
        float4 v0 = make_float4(acc[j][0] + bi0.x, acc[j][1] + bi0.y,
                                acc[j][2] + bi0.z, acc[j][3] + bi0.w);
        float4 v1 = make_float4(acc[j][4] + bi1.x, acc[j][5] + bi1.y,
                                acc[j][6] + bi1.z, acc[j][7] + bi1.w);
        *(float4*)Cp = v0;
        *(float4*)(Cp + 64) = v1;
    }
}

// ---------------- RoPE on q,k segments of qkv (in place) ----------------
// qkv row m = b*S + s, cols: [0,1024) q, [1024,2048) k.
// out[i]    = t[i]*cos - t[i+32]*sin ; out[i+32] = t[i+32]*cos + t[i]*sin
__global__ void rope_kernel(float* __restrict__ qkv)
{
    int idx = blockIdx.x * 256 + threadIdx.x;     // 8192 * 16 * 32 threads
    int i = idx & 31;
    int h = (idx >> 5) & 15;
    int m = idx >> 9;
    int s = m & (S_LEN - 1);
    // inv_freq = 10000^(-i/32); compute in double to land within 1 ulp of fp32 truth
    float inv = (float)exp2(-(double)i * 0.41524101186091903); // log2(10000)/32
    float ang = (float)s * inv;
    float c, sn;
    sincosf(ang, &sn, &c);
    size_t base = (size_t)m * 3072 + (h << 6) + i;
    float q0 = qkv[base], q1 = qkv[base + 32];
    qkv[base]        = q0 * c - q1 * sn;
    qkv[base + 32]   = q1 * c + q0 * sn;
    float k0 = qkv[base + 1024], k1 = qkv[base + 1056];
    qkv[base + 1024] = k0 * c - k1 * sn;
    qkv[base + 1056] = k1 * c + k0 * sn;
}

// ---------------- Flash attention, fp32, Br=Bc=64, D=64 ----------------
#define ASD 68                                        // padded smem row stride
#define ATTN_SMEM (4 * 64 * ASD * 4 + 2048)           // Qs,Ks,Vs,Ps + mask bytes

__global__ __launch_bounds__(256, 2)
void attn_kernel(const float* __restrict__ Qg, const float* __restrict__ Kg,
                 const float* __restrict__ Vg, const unsigned char* __restrict__ maskg,
                 float* __restrict__ Og)
{
    extern __shared__ float smem[];
    float* Qs = smem;
    float* Ks = Qs + 64 * ASD;
    float* Vs = Ks + 64 * ASD;
    float* Ps = Vs + 64 * ASD;
    unsigned char* Ms = (unsigned char*)(Ps + 64 * ASD);

    const int b = blockIdx.z, h = blockIdx.y;
    const int q0 = blockIdx.x << 6;
    const int tid = threadIdx.x;
    const int tx = tid & 15, ty = tid >> 4;

    const size_t bh = (size_t)b * S_LEN * E_DIM + (h << 6);
    const float* Qb = Qg + bh + (size_t)q0 * E_DIM;
    const float* Kb = Kg + bh;
    const float* Vb = Vg + bh;

    // load Q tile (row-major [r][d], padded) + this batch's mask row
#pragma unroll
    for (int t = 0; t < 4; t++) {
        int idx = tid + t * 256;
        int r = idx >> 4, d4 = (idx & 15) << 2;
        *(float4*)&Qs[r * ASD + d4] = *(const float4*)(Qb + (size_t)r * E_DIM + d4);
    }
    {
        const unsigned int* mw = (const unsigned int*)(maskg + (size_t)b * S_LEN);
        unsigned int* msw = (unsigned int*)Ms;
        msw[tid] = mw[tid];
        msw[tid + 256] = mw[tid + 256];
    }

    float mrow[4], lrow[4], o[4][4];
#pragma unroll
    for (int j = 0; j < 4; j++) {
        mrow[j] = -1e30f; lrow[j] = 0.0f;
#pragma unroll
        for (int i = 0; i < 4; i++) o[j][i] = 0.0f;
    }

    for (int kt = 0; kt < 32; kt++) {
        const int kb = kt << 6;
        __syncthreads();   // prev O-phase done; also covers Q/mask load at kt=0
#pragma unroll
        for (int t = 0; t < 4; t++) {
            int idx = tid + t * 256;
            int r = idx >> 4, d4 = (idx & 15) << 2;
            *(float4*)&Ks[r * ASD + d4] = *(const float4*)(Kb + (size_t)(kb + r) * E_DIM + d4);
            *(float4*)&Vs[r * ASD + d4] = *(const float4*)(Vb + (size_t)(kb + r) * E_DIM + d4);
        }
        __syncthreads();

        // S = Q K^T : thread rows 4ty..+3 (contig), cols tx+16i (strided, bank-clean)
        float s[4][4];
#pragma unroll
        for (int j = 0; j < 4; j++)
#pragma unroll
            for (int i = 0; i < 4; i++) s[j][i] = 0.0f;

#pragma unroll 4
        for (int d4 = 0; d4 < 64; d4 += 4) {
            float qq[4][4], kk[4][4];
#pragma unroll
            for (int j = 0; j < 4; j++) {
                float4 t = *(const float4*)&Qs[(4 * ty + j) * ASD + d4];
                qq[j][0] = t.x; qq[j][1] = t.y; qq[j][2] = t.z; qq[j][3] = t.w;
            }
#pragma unroll
            for (int i = 0; i < 4; i++) {
                float4 t = *(const float4*)&Ks[(tx + 16 * i) * ASD + d4];
                kk[i][0] = t.x; kk[i][1] = t.y; kk[i][2] = t.z; kk[i][3] = t.w;
            }
#pragma unroll
            for (int j = 0; j < 4; j++)
#pragma unroll
                for (int i = 0; i < 4; i++)
#pragma unroll
                    for (int dd = 0; dd < 4; dd++)
                        s[j][i] += qq[j][dd] * kk[i][dd];
        }

        bool msk[4];
#pragma unroll
        for (int i = 0; i < 4; i++) msk[i] = Ms[kb + tx + 16 * i] != 0;

        // online softmax (16-lane shuffle groups share a row)
#pragma unroll
        for (int j = 0; j < 4; j++) {
#pragma unroll
            for (int i = 0; i < 4; i++)
                s[j][i] = msk[i] ? -1e30f : s[j][i] * 0.125f;
            float tm = fmaxf(fmaxf(s[j][0], s[j][1]), fmaxf(s[j][2], s[j][3]));
#pragma unroll
            for (int off = 8; off > 0; off >>= 1)
                tm = fmaxf(tm, __shfl_xor_sync(0xffffffffu, tm, off));
            float mn = fmaxf(mrow[j], tm);
            float corr = __expf(mrow[j] - mn);
            mrow[j] = mn;
            float rs = 0.0f;
#pragma unroll
            for (int i = 0; i < 4; i++) { s[j][i] = __expf(s[j][i] - mn); rs += s[j][i]; }
#pragma unroll
            for (int off = 8; off > 0; off >>= 1)
                rs += __shfl_xor_sync(0xffffffffu, rs, off);
            lrow[j] = lrow[j] * corr + rs;
#pragma unroll
            for (int i = 0; i < 4; i++) o[j][i] *= corr;
        }

        // stage P (scalar stores, conflict-free by construction)
#pragma unroll
        for (int j = 0; j < 4; j++)
#pragma unroll
            for (int i = 0; i < 4; i++)
                Ps[(4 * ty + j) * ASD + tx + 16 * i] = s[j][i];
        __syncthreads();

        // O += P @ V : thread rows 4ty..+3, dims 4tx..+3
#pragma unroll 4
        for (int cb = 0; cb < 16; cb++) {
            float pp[4][4], vv[4][4];
#pragma unroll
            for (int j = 0; j < 4; j++) {
                float4 t = *(const float4*)&Ps[(4 * ty + j) * ASD + (cb << 2)];
                pp[j][0] = t.x; pp[j][1] = t.y; pp[j][2] = t.z; pp[j][3] = t.w;
            }
#pragma unroll
            for (int cc = 0; cc < 4; cc++) {
                float4 t = *(const float4*)&Vs[((cb << 2) + cc) * ASD + (tx << 2)];
                vv[cc][0] = t.x; vv[cc][1] = t.y; vv[cc][2] = t.z; vv[cc][3] = t.w;
            }
#pragma unroll
            for (int j = 0; j < 4; j++)
#pragma unroll
                for (int cc = 0; cc < 4; cc++)
#pragma unroll
                    for (int i = 0; i < 4; i++)
                        o[j][i] += pp[j][cc] * vv[cc][i];
        }
    }

    float* Ob = Og + bh + (size_t)q0 * E_DIM;
#pragma unroll
    for (int j = 0; j < 4; j++) {
        float inv = 1.0f / lrow[j];
        float4 r = make_float4(o[j][0] * inv, o[j][1] * inv, o[j][2] * inv, o[j][3] * inv);
        *(float4*)(Ob + (size_t)(4 * ty + j) * E_DIM + (tx << 2)) = r;
    }
}

// ---------------- launch ----------------
extern "C" void kernel_launch(void* const* d_in, const int* in_sizes, int n_in,
                              void* d_out, int out_size)
{
    const float* x     = (const float*)d_in[0];
    const float* w_in  = (const float*)d_in[1];   // (3072,1024)
    const float* b_in  = (const float*)d_in[2];   // (3072,)
    const float* w_out = (const float*)d_in[3];   // (1024,1024)
    const float* b_out = (const float*)d_in[4];   // (1024,)
    const unsigned char* mask = (const unsigned char*)d_in[5]; // (4,2048) bool
    float* out = (float*)d_out;

    float *qkv, *q2, *k2, *v2, *ctx;
    cudaGetSymbolAddress((void**)&qkv, g_qkv);
    cudaGetSymbolAddress((void**)&q2,  g_q2);
    cudaGetSymbolAddress((void**)&k2,  g_k2);
    cudaGetSymbolAddress((void**)&v2,  g_v2);
    cudaGetSymbolAddress((void**)&ctx, g_ctx);

    cudaFuncSetAttribute(attn_kernel, cudaFuncAttributeMaxDynamicSharedMemorySize, ATTN_SMEM);

    // 1) combined = x @ Win^T + b          (8192 x 3072)
    sgemm_nt<<<dim3(24, 64), 256>>>(x, 1024, w_in, 1024, b_in, qkv, 3072, 1024);
    // 2) RoPE on q,k in place
    rope_kernel<<<16384, 256>>>(qkv);
    // 3) redundant second projection q2/k2/v2 (each 8192 x 1024)
    sgemm_nt<<<dim3(8, 64), 256>>>(qkv,        3072, w_in,               1024, b_in,        q2, 1024, 1024);
    sgemm_nt<<<dim3(8, 64), 256>>>(qkv + 1024, 3072, w_in + 1024 * 1024, 1024, b_in + 1024, k2, 1024, 1024);
    sgemm_nt<<<dim3(8, 64), 256>>>(qkv + 2048, 3072, w_in + 2048 * 1024, 1024, b_in + 2048, v2, 1024, 1024);
    // 4) attention -> ctx in (B,S,H,D)
    attn_kernel<<<dim3(32, 16, 4), 256, ATTN_SMEM>>>(q2, k2, v2, mask, ctx);
    // 5) out = ctx @ Wout^T + b
    sgemm_nt<<<dim3(8, 64), 256>>>(ctx, 1024, w_out, 1024, b_out, out, 1024, 1024);
}